// round 8
// baseline (speedup 1.0000x reference)
#include <cuda_runtime.h>
#include <cstdint>

#define T_SEQ  16384
#define IN_DIM 512
#define H_DIM  1024
#define G3     3072           // 3*H
#define NCTA   128            // GRU CTAs
#define NWORK  20             // gemm1 worker CTAs inside fused kernel
#define NSHARD 8
#define NTILE_N (G3 / 128)    // 24 column tiles

// ---------------- scratch (static __device__, no allocations) ----------------
__device__ float g_gx0[(size_t)T_SEQ * G3];     // layer-0 input projection
__device__ float g_gx1[(size_t)T_SEQ * G3];     // layer-1 input projection (worker output)
__device__ float g_h1[(size_t)T_SEQ * H_DIM];
__device__ float g_h2[(size_t)T_SEQ * H_DIM];
__device__ float g_hx[2][H_DIM];                // h exchange (parity double-buffered)
__device__ unsigned g_cnt[2][NSHARD][64];       // sharded arrival counters, 256B stride
__device__ float g_mu[H_DIM];
__device__ float g_rs[H_DIM];
__device__ float g_c[H_DIM];
__device__ float g_off[1];

// packed f32x2 FMA: d = a*b + d (per 32-bit half)
__device__ __forceinline__ void ffma2(unsigned long long& d,
                                      unsigned long long a,
                                      unsigned long long b) {
    asm("fma.rn.f32x2 %0, %1, %2, %0;" : "+l"(d) : "l"(a), "l"(b));
}
__device__ __forceinline__ float hsum2(unsigned long long v) {
    float2 f = *reinterpret_cast<float2*>(&v);
    return f.x + f.y;
}

// ---------------- shared 128x128 tile GEMM body ----------------
// C[bm:bm+128, bn:bn+128] = A[bm:,:K] @ W[bn:,:K]^T + bias[bn:]
// sm: 4096 floats (As 16x128 at 0, Bs 16x128 at 2048)
template<int K>
__device__ void gemm_tile(const float* __restrict__ A, const float* __restrict__ W,
                          const float* __restrict__ bias, float* __restrict__ C,
                          int bm, int bn, float* sm) {
    float* As = sm;
    float* Bs = sm + 2048;
    const int tid = threadIdx.x;
    const int tx = tid & 15, ty = tid >> 4;

    float acc[8][8];
#pragma unroll
    for (int i = 0; i < 8; i++)
#pragma unroll
        for (int j = 0; j < 8; j++) acc[i][j] = 0.f;

    for (int k0 = 0; k0 < K; k0 += 16) {
#pragma unroll
        for (int i = 0; i < 2; i++) {
            int f = tid + i * 256;
            int m = f >> 2;
            int kq = (f & 3) << 2;
            float4 va = *(const float4*)(A + (size_t)(bm + m) * K + k0 + kq);
            As[(kq + 0) * 128 + m] = va.x; As[(kq + 1) * 128 + m] = va.y;
            As[(kq + 2) * 128 + m] = va.z; As[(kq + 3) * 128 + m] = va.w;
            float4 vb = *(const float4*)(W + (size_t)(bn + m) * K + k0 + kq);
            Bs[(kq + 0) * 128 + m] = vb.x; Bs[(kq + 1) * 128 + m] = vb.y;
            Bs[(kq + 2) * 128 + m] = vb.z; Bs[(kq + 3) * 128 + m] = vb.w;
        }
        __syncthreads();
#pragma unroll
        for (int kk = 0; kk < 16; kk++) {
            float a[8], b[8];
            *(float4*)(a)     = *(const float4*)&As[kk * 128 + ty * 8];
            *(float4*)(a + 4) = *(const float4*)&As[kk * 128 + ty * 8 + 4];
            *(float4*)(b)     = *(const float4*)&Bs[kk * 128 + tx * 8];
            *(float4*)(b + 4) = *(const float4*)&Bs[kk * 128 + tx * 8 + 4];
#pragma unroll
            for (int i = 0; i < 8; i++)
#pragma unroll
                for (int j = 0; j < 8; j++)
                    acc[i][j] = fmaf(a[i], b[j], acc[i][j]);
        }
        __syncthreads();
    }
#pragma unroll
    for (int i = 0; i < 8; i++) {
        int m = bm + ty * 8 + i;
#pragma unroll
        for (int j = 0; j < 8; j += 4) {
            int n = bn + tx * 8 + j;
            float4 o;
            o.x = acc[i][j + 0] + bias[n + 0];
            o.y = acc[i][j + 1] + bias[n + 1];
            o.z = acc[i][j + 2] + bias[n + 2];
            o.w = acc[i][j + 3] + bias[n + 3];
            *(float4*)(C + (size_t)m * G3 + n) = o;
        }
    }
}

// ---------------- layer-0 GEMM kernel (also resets sharded counters) ----------------
__global__ __launch_bounds__(256) void k_gemm0(const float* __restrict__ x,
                                               const float* __restrict__ W,
                                               const float* __restrict__ bias) {
    __shared__ float sm[4096];
    if (blockIdx.x == 0 && blockIdx.y == 0 && threadIdx.x < 16)
        g_cnt[threadIdx.x >> 3][threadIdx.x & 7][0] = 0u;
    gemm_tile<IN_DIM>(x, W, bias, g_gx0, blockIdx.y * 128, blockIdx.x * 128, sm);
}

// ---------------- GRU recurrence body (sharded-counter handshake) ----------------
// B0/B1: compile-time counter bases (monotonic counters persist across layers).
// Arm: each CTA publishes h0=0 for its slots + one release-arrival to cnt[0].
template<unsigned B0, unsigned B1>
__device__ void gru_body(const float* __restrict__ w_hh, const float* __restrict__ b_hh,
                         const float* __restrict__ gx, float* __restrict__ h_out,
                         float* sm) {
    float* hs = sm;   // 1024 floats
    const int tid  = threadIdx.x;
    const int warp = tid >> 5;
    const int lane = tid & 31;
    const int j = blockIdx.x * 8 + warp;
    const int shard = blockIdx.x & (NSHARD - 1);

    // Packed recurrent weights: wX2[k] = {w[2*lane+64k], w[2*lane+64k+1]}
    unsigned long long wr2[16], wz2[16], wn2[16];
    {
        const float* pr = w_hh + (size_t)j * H_DIM + 2 * lane;
        const float* pz = w_hh + (size_t)(H_DIM + j) * H_DIM + 2 * lane;
        const float* pn = w_hh + (size_t)(2 * H_DIM + j) * H_DIM + 2 * lane;
#pragma unroll
        for (int k = 0; k < 16; k++) {
            wr2[k] = *(const unsigned long long*)(pr + 64 * k);
            wz2[k] = *(const unsigned long long*)(pz + 64 * k);
            wn2[k] = *(const unsigned long long*)(pn + 64 * k);
        }
    }
    float bhr = 0.f, bhz = 0.f, bhn = 0.f;
    float gxr = 0.f, gxz = 0.f, gxn = 0.f;
    if (lane == 0) {
        bhr = b_hh[j]; bhz = b_hh[H_DIM + j]; bhn = b_hh[2 * H_DIM + j];
        gxr = __ldg(gx + j); gxz = __ldg(gx + H_DIM + j); gxn = __ldg(gx + 2 * H_DIM + j);
        // arm: h0 = 0 for this CTA's slots
        asm volatile("st.relaxed.gpu.f32 [%0], %1;" :: "l"(&g_hx[0][j]), "f"(0.f) : "memory");
    }
    __syncthreads();
    if (tid == 0)
        asm volatile("red.release.gpu.global.add.u32 [%0], %1;"
                     :: "l"(&g_cnt[0][shard][0]), "r"(1u) : "memory");

    for (int t = 0; t < T_SEQ; t++) {
        const int par = t & 1;

        // ---- readiness: thread0 sums 8 relaxed shard reads, then acquire fence ----
        if (tid == 0) {
            const unsigned target = (par ? B1 : B0) + 128u * ((unsigned)(t >> 1) + 1u);
            for (;;) {
                unsigned s = 0, v;
#pragma unroll
                for (int k = 0; k < NSHARD; k++) {
                    asm volatile("ld.relaxed.gpu.u32 %0, [%1];"
                                 : "=r"(v) : "l"(&g_cnt[par][k][0]) : "memory");
                    s += v;
                }
                if (s >= target) break;
            }
            asm volatile("fence.acq_rel.gpu;" ::: "memory");
        }
        __syncthreads();

        // ---- bulk load h(t): one burst, 16B/thread ----
        {
            const unsigned long long* src = (const unsigned long long*)g_hx[par] + tid * 2;
            unsigned long long u0, u1;
            asm volatile("ld.relaxed.gpu.b64 %0, [%1];" : "=l"(u0) : "l"(src + 0) : "memory");
            asm volatile("ld.relaxed.gpu.b64 %0, [%1];" : "=l"(u1) : "l"(src + 1) : "memory");
            ((unsigned long long*)hs)[tid * 2 + 0] = u0;
            ((unsigned long long*)hs)[tid * 2 + 1] = u1;
        }
        __syncthreads();

        // ---- packed dot products ----
        unsigned long long aR2 = 0ull, aZ2 = 0ull, aN2 = 0ull;
        const unsigned long long* hp = (const unsigned long long*)hs;
#pragma unroll
        for (int k = 0; k < 16; k++) {
            unsigned long long h2 = hp[lane + 32 * k];
            ffma2(aR2, wr2[k], h2);
            ffma2(aZ2, wz2[k], h2);
            ffma2(aN2, wn2[k], h2);
        }
        float aR = hsum2(aR2), aZ = hsum2(aZ2), aN = hsum2(aN2);
#pragma unroll
        for (int off = 16; off > 0; off >>= 1) {
            aR += __shfl_xor_sync(0xffffffffu, aR, off);
            aZ += __shfl_xor_sync(0xffffffffu, aZ, off);
            aN += __shfl_xor_sync(0xffffffffu, aN, off);
        }

        if (lane == 0) {
            float r = 1.f / (1.f + __expf(-(gxr + aR + bhr)));
            float z = 1.f / (1.f + __expf(-(gxz + aZ + bhz)));
            float npre = gxn + r * (aN + bhn);
            npre = fminf(fmaxf(npre, -20.f), 20.f);
            float e = __expf(-2.f * npre);
            float n = (1.f - e) / (1.f + e);
            float hprev = hs[j];
            float hnew = (1.f - z) * n + z * hprev;

            asm volatile("st.relaxed.gpu.f32 [%0], %1;"
                         :: "l"(&g_hx[par ^ 1][j]), "f"(hnew) : "memory");
            h_out[(size_t)t * H_DIM + j] = hnew;   // must precede red (workers consume)
        }
        __syncthreads();   // all 8 publishes + h_out stores of this CTA done

        if (tid == 0)
            asm volatile("red.release.gpu.global.add.u32 [%0], %1;"
                         :: "l"(&g_cnt[par ^ 1][shard][0]), "r"(1u) : "memory");

        // gx prefetch for next step — off the pre-release path
        if (lane == 0) {
            int tn = (t + 1 < T_SEQ) ? (t + 1) : t;
            const float* gp = gx + (size_t)tn * G3;
            gxr = __ldg(gp + j); gxz = __ldg(gp + H_DIM + j); gxn = __ldg(gp + 2 * H_DIM + j);
        }
    }
}

// ---------------- worker body: gemm1 tiles gated on recurrence progress ----------------
__device__ void worker_body(const float* __restrict__ w_ih1,
                            const float* __restrict__ b_ih1, float* sm) {
    const int w0 = blockIdx.x - NCTA;
    int gated_r = -1;
    for (int tt = w0; tt < 128 * NTILE_N; tt += NWORK) {
        const int r = tt / NTILE_N, c = tt % NTILE_N;
        if (r != gated_r) {
            if (threadIdx.x == 0) {
                // need h1 rows < 128*(r+1): sum of all 16 shards >= 128*(128*(r+1)+1)
                const unsigned thr = 128u * (128u * (unsigned)(r + 1) + 1u);
                for (;;) {
                    unsigned s = 0, v;
#pragma unroll
                    for (int p = 0; p < 2; p++)
#pragma unroll
                        for (int k = 0; k < NSHARD; k++) {
                            asm volatile("ld.relaxed.gpu.u32 %0, [%1];"
                                         : "=r"(v) : "l"(&g_cnt[p][k][0]) : "memory");
                            s += v;
                        }
                    if (s >= thr) break;
                }
                asm volatile("fence.acq_rel.gpu;" ::: "memory");
            }
            __syncthreads();
            gated_r = r;
        }
        gemm_tile<H_DIM>(g_h1, w_ih1, b_ih1, g_gx1, r * 128, c * 128, sm);
    }
}

// ---------------- fused: layer-0 recurrence + layer-1 input GEMM ----------------
__global__ __launch_bounds__(256, 1) void k_fused0(const float* __restrict__ w_hh0,
                                                   const float* __restrict__ b_hh0,
                                                   const float* __restrict__ w_ih1,
                                                   const float* __restrict__ b_ih1) {
    __shared__ float sm[4096];
    if (blockIdx.x < NCTA)
        gru_body<0u, 0u>(w_hh0, b_hh0, g_gx0, g_h1, sm);
    else
        worker_body(w_ih1, b_ih1, sm);
}

// ---------------- layer-1 recurrence (counters continue monotonically) ----------------
// After fused0: cnt[0] = 128*8193 (arm + 8192 odd-step publishes), cnt[1] = 128*8192.
__global__ __launch_bounds__(256, 1) void k_gru1(const float* __restrict__ w_hh1,
                                                 const float* __restrict__ b_hh1) {
    __shared__ float sm[4096];
    gru_body<128u * 8193u, 128u * 8192u>(w_hh1, b_hh1, g_gx1, g_h2, sm);
}

// ---------------- BatchNorm statistics over T per feature ----------------
__global__ __launch_bounds__(256) void k_bnstats() {
    __shared__ float ssum[256], ssq[256];
    const int f  = blockIdx.x * 32 + (threadIdx.x & 31);
    const int ty = threadIdx.x >> 5;
    float s = 0.f, q = 0.f;
    for (int t = ty; t < T_SEQ; t += 8) {
        float v = g_h2[(size_t)t * H_DIM + f];
        s += v; q = fmaf(v, v, q);
    }
    ssum[threadIdx.x] = s; ssq[threadIdx.x] = q;
    __syncthreads();
    if (ty == 0) {
#pragma unroll
        for (int k = 1; k < 8; k++) { s += ssum[threadIdx.x + 32 * k]; q += ssq[threadIdx.x + 32 * k]; }
        float mu  = s * (1.f / T_SEQ);
        float var = q * (1.f / T_SEQ) - mu * mu;
        g_mu[f] = mu;
        g_rs[f] = rsqrtf(var + 1e-5f);
    }
}

// ---------------- fold BN + fc into per-feature coefficient + scalar offset ----------------
__global__ __launch_bounds__(256) void k_coeff(const float* __restrict__ gamma,
                                               const float* __restrict__ beta,
                                               const float* __restrict__ fcw,
                                               const float* __restrict__ fcb) {
    __shared__ float red[256];
    float part = 0.f;
    for (int j = threadIdx.x; j < H_DIM; j += 256) {
        float rs = g_rs[j];
        float c = gamma[j] * rs * fcw[j];
        g_c[j] = c;
        part += beta[j] * fcw[j] - g_mu[j] * c;
    }
    red[threadIdx.x] = part;
    __syncthreads();
    for (int k = 128; k > 0; k >>= 1) {
        if (threadIdx.x < k) red[threadIdx.x] += red[threadIdx.x + k];
        __syncthreads();
    }
    if (threadIdx.x == 0) g_off[0] = fcb[0] + red[0];
}

// ---------------- head: y[t] = dot(h2[t], c) + off ----------------
__global__ __launch_bounds__(256) void k_head(float* __restrict__ y) {
    __shared__ float cs[H_DIM];
    for (int i = threadIdx.x; i < H_DIM; i += 256) cs[i] = g_c[i];
    __syncthreads();
    const int warp = threadIdx.x >> 5, lane = threadIdx.x & 31;
    const int t = blockIdx.x * 8 + warp;
    const float* row = g_h2 + (size_t)t * H_DIM;
    float s = 0.f;
#pragma unroll
    for (int k = 0; k < 32; k++) s = fmaf(row[lane + 32 * k], cs[lane + 32 * k], s);
#pragma unroll
    for (int off = 16; off > 0; off >>= 1) s += __shfl_xor_sync(0xffffffffu, s, off);
    if (lane == 0) y[t] = s + g_off[0];
}

// ---------------- launch ----------------
extern "C" void kernel_launch(void* const* d_in, const int* in_sizes, int n_in,
                              void* d_out, int out_size) {
    const float* x     = (const float*)d_in[0];
    const float* w_ih0 = (const float*)d_in[1];
    const float* w_hh0 = (const float*)d_in[2];
    const float* b_ih0 = (const float*)d_in[3];
    const float* b_hh0 = (const float*)d_in[4];
    const float* w_ih1 = (const float*)d_in[5];
    const float* w_hh1 = (const float*)d_in[6];
    const float* b_ih1 = (const float*)d_in[7];
    const float* b_hh1 = (const float*)d_in[8];
    const float* gamma = (const float*)d_in[9];
    const float* beta  = (const float*)d_in[10];
    const float* fcw   = (const float*)d_in[11];
    const float* fcb   = (const float*)d_in[12];
    float* y = (float*)d_out;

    dim3 ggrid(G3 / 128, T_SEQ / 128);

    k_gemm0<<<ggrid, 256>>>(x, w_ih0, b_ih0);                       // resets counters too
    k_fused0<<<NCTA + NWORK, 256>>>(w_hh0, b_hh0, w_ih1, b_ih1);    // gru0 + hidden gemm1
    k_gru1<<<NCTA, 256>>>(w_hh1, b_hh1);
    k_bnstats<<<32, 256>>>();
    k_coeff<<<1, 256>>>(gamma, beta, fcw, fcb);
    k_head<<<T_SEQ / 8, 256>>>(y);
}

// round 10
// speedup vs baseline: 1.1691x; 1.1691x over previous
#include <cuda_runtime.h>
#include <cstdint>

#define T_SEQ  16384
#define IN_DIM 512
#define H_DIM  1024
#define G3     3072           // 3*H
#define NCTA   128            // GRU CTAs
#define NWORK  20             // gemm1 worker CTAs inside fused kernel
#define NTILE_N (G3 / 128)    // 24 column tiles
#define WROWS  96             // row-tiles of gemm1 done by workers (rest: trailing kernel)

// ---------------- scratch (static __device__, no allocations) ----------------
__device__ float g_gx0[(size_t)T_SEQ * G3];
__device__ float g_gx1[(size_t)T_SEQ * G3];
__device__ float g_h1[(size_t)T_SEQ * H_DIM];
__device__ float g_h2[(size_t)T_SEQ * H_DIM];
__device__ float g_hx[2][H_DIM];                // h exchange (parity double-buffered)
__device__ unsigned g_cnt[2];                   // per-parity arrival counters (monotonic)
__device__ float g_mu[H_DIM];
__device__ float g_rs[H_DIM];
__device__ float g_c[H_DIM];
__device__ float g_off[1];

// packed f32x2 FMA: d = a*b + d (per 32-bit half)
__device__ __forceinline__ void ffma2(unsigned long long& d,
                                      unsigned long long a,
                                      unsigned long long b) {
    asm("fma.rn.f32x2 %0, %1, %2, %0;" : "+l"(d) : "l"(a), "l"(b));
}
__device__ __forceinline__ float hsum2(unsigned long long v) {
    float2 f = *reinterpret_cast<float2*>(&v);
    return f.x + f.y;
}

// ---------------- no-op (aligns ncu's captured-launch index onto the fused kernel) ----
__global__ void k_nop() {}

// ---------------- shared 128x128 tile GEMM body ----------------
template<int K>
__device__ void gemm_tile(const float* __restrict__ A, const float* __restrict__ W,
                          const float* __restrict__ bias, float* __restrict__ C,
                          int bm, int bn, float* sm) {
    float* As = sm;
    float* Bs = sm + 2048;
    const int tid = threadIdx.x;
    const int tx = tid & 15, ty = tid >> 4;

    float acc[8][8];
#pragma unroll
    for (int i = 0; i < 8; i++)
#pragma unroll
        for (int j = 0; j < 8; j++) acc[i][j] = 0.f;

    for (int k0 = 0; k0 < K; k0 += 16) {
#pragma unroll
        for (int i = 0; i < 2; i++) {
            int f = tid + i * 256;
            int m = f >> 2;
            int kq = (f & 3) << 2;
            float4 va = *(const float4*)(A + (size_t)(bm + m) * K + k0 + kq);
            As[(kq + 0) * 128 + m] = va.x; As[(kq + 1) * 128 + m] = va.y;
            As[(kq + 2) * 128 + m] = va.z; As[(kq + 3) * 128 + m] = va.w;
            float4 vb = *(const float4*)(W + (size_t)(bn + m) * K + k0 + kq);
            Bs[(kq + 0) * 128 + m] = vb.x; Bs[(kq + 1) * 128 + m] = vb.y;
            Bs[(kq + 2) * 128 + m] = vb.z; Bs[(kq + 3) * 128 + m] = vb.w;
        }
        __syncthreads();
#pragma unroll
        for (int kk = 0; kk < 16; kk++) {
            float a[8], b[8];
            *(float4*)(a)     = *(const float4*)&As[kk * 128 + ty * 8];
            *(float4*)(a + 4) = *(const float4*)&As[kk * 128 + ty * 8 + 4];
            *(float4*)(b)     = *(const float4*)&Bs[kk * 128 + tx * 8];
            *(float4*)(b + 4) = *(const float4*)&Bs[kk * 128 + tx * 8 + 4];
#pragma unroll
            for (int i = 0; i < 8; i++)
#pragma unroll
                for (int j = 0; j < 8; j++)
                    acc[i][j] = fmaf(a[i], b[j], acc[i][j]);
        }
        __syncthreads();
    }
#pragma unroll
    for (int i = 0; i < 8; i++) {
        int m = bm + ty * 8 + i;
#pragma unroll
        for (int j = 0; j < 8; j += 4) {
            int n = bn + tx * 8 + j;
            float4 o;
            o.x = acc[i][j + 0] + bias[n + 0];
            o.y = acc[i][j + 1] + bias[n + 1];
            o.z = acc[i][j + 2] + bias[n + 2];
            o.w = acc[i][j + 3] + bias[n + 3];
            *(float4*)(C + (size_t)m * G3 + n) = o;
        }
    }
}

// ---------------- layer-0 GEMM kernel (also resets counters) ----------------
__global__ __launch_bounds__(256) void k_gemm0(const float* __restrict__ x,
                                               const float* __restrict__ W,
                                               const float* __restrict__ bias) {
    __shared__ float sm[4096];
    if (blockIdx.x == 0 && blockIdx.y == 0 && threadIdx.x < 2)
        g_cnt[threadIdx.x] = 0u;
    gemm_tile<IN_DIM>(x, W, bias, g_gx0, blockIdx.y * 128, blockIdx.x * 128, sm);
}

// ---------------- GRU recurrence body (single-counter handshake, R7-proven) ----------------
// B0/B1: compile-time counter bases (counters are monotonic across layers).
template<unsigned B0, unsigned B1>
__device__ void gru_body(const float* __restrict__ w_hh, const float* __restrict__ b_hh,
                         const float* __restrict__ gx, float* __restrict__ h_out,
                         float* sm) {
    float* hs = sm;   // 1024 floats
    const int tid  = threadIdx.x;
    const int warp = tid >> 5;
    const int lane = tid & 31;
    const int j = blockIdx.x * 8 + warp;

    // Packed recurrent weights: wX2[k] = {w[2*lane+64k], w[2*lane+64k+1]}
    unsigned long long wr2[16], wz2[16], wn2[16];
    {
        const float* pr = w_hh + (size_t)j * H_DIM + 2 * lane;
        const float* pz = w_hh + (size_t)(H_DIM + j) * H_DIM + 2 * lane;
        const float* pn = w_hh + (size_t)(2 * H_DIM + j) * H_DIM + 2 * lane;
#pragma unroll
        for (int k = 0; k < 16; k++) {
            wr2[k] = *(const unsigned long long*)(pr + 64 * k);
            wz2[k] = *(const unsigned long long*)(pz + 64 * k);
            wn2[k] = *(const unsigned long long*)(pn + 64 * k);
        }
    }
    float bhr = 0.f, bhz = 0.f, bhn = 0.f;
    float gxr = 0.f, gxz = 0.f, gxn = 0.f;
    if (lane == 0) {
        bhr = b_hh[j]; bhz = b_hh[H_DIM + j]; bhn = b_hh[2 * H_DIM + j];
        gxr = __ldg(gx + j); gxz = __ldg(gx + H_DIM + j); gxn = __ldg(gx + 2 * H_DIM + j);
        // arm: h0 = 0 for this CTA's slots
        asm volatile("st.relaxed.gpu.f32 [%0], %1;" :: "l"(&g_hx[0][j]), "f"(0.f) : "memory");
    }
    __syncthreads();
    if (tid == 0)
        asm volatile("red.release.gpu.global.add.u32 [%0], %1;"
                     :: "l"(&g_cnt[0]), "r"(1u) : "memory");

    for (int t = 0; t < T_SEQ; t++) {
        const int par = t & 1;

        // ---- readiness: thread0 polls the single parity counter (acquire) ----
        if (tid == 0) {
            const unsigned target = (par ? B1 : B0) + 128u * ((unsigned)(t >> 1) + 1u);
            unsigned c;
            do {
                asm volatile("ld.acquire.gpu.u32 %0, [%1];"
                             : "=r"(c) : "l"(&g_cnt[par]) : "memory");
            } while (c < target);
        }
        __syncthreads();

        // ---- bulk load h(t): one burst, 16B/thread ----
        {
            const unsigned long long* src = (const unsigned long long*)g_hx[par] + tid * 2;
            unsigned long long u0, u1;
            asm volatile("ld.relaxed.gpu.b64 %0, [%1];" : "=l"(u0) : "l"(src + 0) : "memory");
            asm volatile("ld.relaxed.gpu.b64 %0, [%1];" : "=l"(u1) : "l"(src + 1) : "memory");
            ((unsigned long long*)hs)[tid * 2 + 0] = u0;
            ((unsigned long long*)hs)[tid * 2 + 1] = u1;
        }
        __syncthreads();

        // ---- packed dot products ----
        unsigned long long aR2 = 0ull, aZ2 = 0ull, aN2 = 0ull;
        const unsigned long long* hp = (const unsigned long long*)hs;
#pragma unroll
        for (int k = 0; k < 16; k++) {
            unsigned long long h2 = hp[lane + 32 * k];
            ffma2(aR2, wr2[k], h2);
            ffma2(aZ2, wz2[k], h2);
            ffma2(aN2, wn2[k], h2);
        }
        float aR = hsum2(aR2), aZ = hsum2(aZ2), aN = hsum2(aN2);
#pragma unroll
        for (int off = 16; off > 0; off >>= 1) {
            aR += __shfl_xor_sync(0xffffffffu, aR, off);
            aZ += __shfl_xor_sync(0xffffffffu, aZ, off);
            aN += __shfl_xor_sync(0xffffffffu, aN, off);
        }

        if (lane == 0) {
            float r = 1.f / (1.f + __expf(-(gxr + aR + bhr)));
            float z = 1.f / (1.f + __expf(-(gxz + aZ + bhz)));
            float npre = gxn + r * (aN + bhn);
            npre = fminf(fmaxf(npre, -20.f), 20.f);
            float e = __expf(-2.f * npre);
            float n = (1.f - e) / (1.f + e);
            float hprev = hs[j];
            float hnew = (1.f - z) * n + z * hprev;

            asm volatile("st.relaxed.gpu.f32 [%0], %1;"
                         :: "l"(&g_hx[par ^ 1][j]), "f"(hnew) : "memory");
            h_out[(size_t)t * H_DIM + j] = hnew;   // must precede red (workers consume)
        }
        __syncthreads();   // all 8 publishes + h_out stores of this CTA done

        if (tid == 0)
            asm volatile("red.release.gpu.global.add.u32 [%0], %1;"
                         :: "l"(&g_cnt[par ^ 1]), "r"(1u) : "memory");

        // gx prefetch for next step — off the pre-release path
        if (lane == 0) {
            int tn = (t + 1 < T_SEQ) ? (t + 1) : t;
            const float* gp = gx + (size_t)tn * G3;
            gxr = __ldg(gp + j); gxz = __ldg(gp + H_DIM + j); gxn = __ldg(gp + 2 * H_DIM + j);
        }
    }
}

// ---------------- worker body: first WROWS row-tiles of gemm1, gated on progress ----------------
__device__ void worker_body(const float* __restrict__ w_ih1,
                            const float* __restrict__ b_ih1, float* sm) {
    const int w0 = blockIdx.x - NCTA;
    int gated_r = -1;
    for (int tt = w0; tt < WROWS * NTILE_N; tt += NWORK) {
        const int r = tt / NTILE_N, c = tt % NTILE_N;
        if (r != gated_r) {
            if (threadIdx.x == 0) {
                // need h1 rows < 128*(r+1): cnt0+cnt1 >= 128*(128*(r+1)+1)  (+1 = arm)
                const unsigned thr = 128u * (128u * (unsigned)(r + 1) + 1u);
                for (;;) {
                    unsigned a, b;
                    asm volatile("ld.relaxed.gpu.v2.u32 {%0,%1}, [%2];"
                                 : "=r"(a), "=r"(b) : "l"(&g_cnt[0]) : "memory");
                    if (a + b >= thr) break;
                }
                asm volatile("fence.acq_rel.gpu;" ::: "memory");
            }
            __syncthreads();
            gated_r = r;
        }
        gemm_tile<H_DIM>(g_h1, w_ih1, b_ih1, g_gx1, r * 128, c * 128, sm);
    }
}

// ---------------- fused: layer-0 recurrence + partial layer-1 input GEMM ----------------
__global__ __launch_bounds__(256, 1) void k_fused0(const float* __restrict__ w_hh0,
                                                   const float* __restrict__ b_hh0,
                                                   const float* __restrict__ w_ih1,
                                                   const float* __restrict__ b_ih1) {
    __shared__ float sm[4096];
    if (blockIdx.x < NCTA)
        gru_body<0u, 0u>(w_hh0, b_hh0, g_gx0, g_h1, sm);
    else
        worker_body(w_ih1, b_ih1, sm);
}

// ---------------- trailing gemm1: remaining row-tiles at full grid ----------------
__global__ __launch_bounds__(256) void k_gemm1b(const float* __restrict__ w_ih1,
                                                const float* __restrict__ b_ih1) {
    __shared__ float sm[4096];
    gemm_tile<H_DIM>(g_h1, w_ih1, b_ih1, g_gx1,
                     (WROWS + blockIdx.y) * 128, blockIdx.x * 128, sm);
}

// ---------------- layer-1 recurrence (counters continue monotonically) ----------------
// After fused0: cnt[0] = 128*8193 (arm + 8192 odd publishes), cnt[1] = 128*8192.
__global__ __launch_bounds__(256, 1) void k_gru1(const float* __restrict__ w_hh1,
                                                 const float* __restrict__ b_hh1) {
    __shared__ float sm[4096];
    gru_body<128u * 8193u, 128u * 8192u>(w_hh1, b_hh1, g_gx1, g_h2, sm);
}

// ---------------- BatchNorm statistics over T per feature ----------------
__global__ __launch_bounds__(256) void k_bnstats() {
    __shared__ float ssum[256], ssq[256];
    const int f  = blockIdx.x * 32 + (threadIdx.x & 31);
    const int ty = threadIdx.x >> 5;
    float s = 0.f, q = 0.f;
    for (int t = ty; t < T_SEQ; t += 8) {
        float v = g_h2[(size_t)t * H_DIM + f];
        s += v; q = fmaf(v, v, q);
    }
    ssum[threadIdx.x] = s; ssq[threadIdx.x] = q;
    __syncthreads();
    if (ty == 0) {
#pragma unroll
        for (int k = 1; k < 8; k++) { s += ssum[threadIdx.x + 32 * k]; q += ssq[threadIdx.x + 32 * k]; }
        float mu  = s * (1.f / T_SEQ);
        float var = q * (1.f / T_SEQ) - mu * mu;
        g_mu[f] = mu;
        g_rs[f] = rsqrtf(var + 1e-5f);
    }
}

// ---------------- fold BN + fc into per-feature coefficient + scalar offset ----------------
__global__ __launch_bounds__(256) void k_coeff(const float* __restrict__ gamma,
                                               const float* __restrict__ beta,
                                               const float* __restrict__ fcw,
                                               const float* __restrict__ fcb) {
    __shared__ float red[256];
    float part = 0.f;
    for (int j = threadIdx.x; j < H_DIM; j += 256) {
        float rs = g_rs[j];
        float c = gamma[j] * rs * fcw[j];
        g_c[j] = c;
        part += beta[j] * fcw[j] - g_mu[j] * c;
    }
    red[threadIdx.x] = part;
    __syncthreads();
    for (int k = 128; k > 0; k >>= 1) {
        if (threadIdx.x < k) red[threadIdx.x] += red[threadIdx.x + k];
        __syncthreads();
    }
    if (threadIdx.x == 0) g_off[0] = fcb[0] + red[0];
}

// ---------------- head: y[t] = dot(h2[t], c) + off ----------------
__global__ __launch_bounds__(256) void k_head(float* __restrict__ y) {
    __shared__ float cs[H_DIM];
    for (int i = threadIdx.x; i < H_DIM; i += 256) cs[i] = g_c[i];
    __syncthreads();
    const int warp = threadIdx.x >> 5, lane = threadIdx.x & 31;
    const int t = blockIdx.x * 8 + warp;
    const float* row = g_h2 + (size_t)t * H_DIM;
    float s = 0.f;
#pragma unroll
    for (int k = 0; k < 32; k++) s = fmaf(row[lane + 32 * k], cs[lane + 32 * k], s);
#pragma unroll
    for (int off = 16; off > 0; off >>= 1) s += __shfl_xor_sync(0xffffffffu, s, off);
    if (lane == 0) y[t] = s + g_off[0];
}

// ---------------- launch ----------------
extern "C" void kernel_launch(void* const* d_in, const int* in_sizes, int n_in,
                              void* d_out, int out_size) {
    const float* x     = (const float*)d_in[0];
    const float* w_ih0 = (const float*)d_in[1];
    const float* w_hh0 = (const float*)d_in[2];
    const float* b_ih0 = (const float*)d_in[3];
    const float* b_hh0 = (const float*)d_in[4];
    const float* w_ih1 = (const float*)d_in[5];
    const float* w_hh1 = (const float*)d_in[6];
    const float* b_ih1 = (const float*)d_in[7];
    const float* b_hh1 = (const float*)d_in[8];
    const float* gamma = (const float*)d_in[9];
    const float* beta  = (const float*)d_in[10];
    const float* fcw   = (const float*)d_in[11];
    const float* fcb   = (const float*)d_in[12];
    float* y = (float*)d_out;

    dim3 ggrid(G3 / 128, T_SEQ / 128);
    dim3 grid1b(NTILE_N, (T_SEQ / 128) - WROWS);

    k_gemm0<<<ggrid, 256>>>(x, w_ih0, b_ih0);                       // #1 (resets counters)
    k_nop<<<1, 32>>>();                                             // #2 (ncu alignment)
    k_nop<<<1, 32>>>();                                             // #3 (ncu alignment)
    k_fused0<<<NCTA + NWORK, 256>>>(w_hh0, b_hh0, w_ih1, b_ih1);    // #4 <- profiled
    k_gemm1b<<<grid1b, 256>>>(w_ih1, b_ih1);                        // #5 remaining tiles
    k_gru1<<<NCTA, 256>>>(w_hh1, b_hh1);                            // #6
    k_bnstats<<<32, 256>>>();                                       // #7
    k_coeff<<<1, 256>>>(gamma, beta, fcw, fcb);                     // #8
    k_head<<<T_SEQ / 8, 256>>>(y);                                  // #9
}